// round 15
// baseline (speedup 1.0000x reference)
#include <cuda_runtime.h>
#include <cuda_fp16.h>

// Problem constants
#define B_ 4
#define L_ 1024
#define C_ 768
#define H_ 12
#define D_ 64
#define M_ (B_ * L_)      // 4096
#define NQKV_ (3 * C_)    // 2304

// Scratch (device globals; no allocation allowed)
__device__ __half g_q[B_ * H_ * L_ * D_];   // [B,H,L,D], fp16, q pre-scaled
__device__ __half g_k[B_ * H_ * L_ * D_];   // [B,H,L,D], fp16
__device__ __half g_vt[B_ * H_ * D_ * L_];  // [B,H,D,L]  V TRANSPOSED, fp16
__device__ __half g_o[M_ * C_];             // attention output, fp16
__device__ __half g_x[M_ * C_];             // fp16 x
__device__ __half g_wqkv[NQKV_ * C_];       // fp16 w_qkv
__device__ __half g_wproj[C_ * C_];         // fp16 w_proj

// ---- helpers -----------------------------------------------------------
__device__ __forceinline__ unsigned f2h2(float lo, float hi) {
    __half2 h = __floats2half2_rn(lo, hi);
    return *(unsigned*)&h;
}

// mma.m16n8k16 row.col f32 += f16*f16
__device__ __forceinline__ void mma16(float* c, unsigned a0, unsigned a1,
                                      unsigned a2, unsigned a3,
                                      unsigned b0, unsigned b1) {
    asm volatile(
        "mma.sync.aligned.m16n8k16.row.col.f32.f16.f16.f32 "
        "{%0,%1,%2,%3},{%4,%5,%6,%7},{%8,%9},{%0,%1,%2,%3};"
        : "+f"(c[0]), "+f"(c[1]), "+f"(c[2]), "+f"(c[3])
        : "r"(a0), "r"(a1), "r"(a2), "r"(a3), "r"(b0), "r"(b1));
}
__device__ __forceinline__ void ldm4(unsigned* d, const __half* p) {
    unsigned sa = (unsigned)__cvta_generic_to_shared(p);
    asm volatile("ldmatrix.sync.aligned.m8n8.x4.shared.b16 {%0,%1,%2,%3}, [%4];"
        : "=r"(d[0]), "=r"(d[1]), "=r"(d[2]), "=r"(d[3]) : "r"(sa));
}
__device__ __forceinline__ void ldm2(unsigned* d, const __half* p) {
    unsigned sa = (unsigned)__cvta_generic_to_shared(p);
    asm volatile("ldmatrix.sync.aligned.m8n8.x2.shared.b16 {%0,%1}, [%2];"
        : "=r"(d[0]), "=r"(d[1]) : "r"(sa));
}
__device__ __forceinline__ void cpa16(void* s, const void* g) {
    unsigned sa = (unsigned)__cvta_generic_to_shared(s);
    asm volatile("cp.async.cg.shared.global [%0], [%1], 16;" :: "r"(sa), "l"(g));
}
__device__ __forceinline__ void cp_commit() {
    asm volatile("cp.async.commit_group;" ::: "memory");
}
__device__ __forceinline__ void cp_wait1() {
    asm volatile("cp.async.wait_group 1;" ::: "memory");
}
__device__ __forceinline__ void cp_wait0() {
    asm volatile("cp.async.wait_group 0;" ::: "memory");
}

// ---------------------------------------------------------------------------
// Kernel 0: convert x, w_qkv, w_proj to fp16.
// ---------------------------------------------------------------------------
#define NX4  (M_ * C_ / 4)
#define NWQ4 (NQKV_ * C_ / 4)
#define NWP4 (C_ * C_ / 4)
__global__ __launch_bounds__(256) void round_fp16(const float* __restrict__ x,
                                                  const float* __restrict__ wq,
                                                  const float* __restrict__ wp)
{
    int i = blockIdx.x * 256 + threadIdx.x;
    const float4* src;
    unsigned* dst;
    int j;
    if (i < NX4)                  { src = (const float4*)x;  dst = (unsigned*)g_x;     j = i; }
    else if (i < NX4 + NWQ4)      { src = (const float4*)wq; dst = (unsigned*)g_wqkv;  j = i - NX4; }
    else                          { src = (const float4*)wp; dst = (unsigned*)g_wproj; j = i - NX4 - NWQ4; }
    float4 v = src[j];
    dst[j * 2]     = f2h2(v.x, v.y);
    dst[j * 2 + 1] = f2h2(v.z, v.w);
}

// ---------------------------------------------------------------------------
// QKV GEMM (fp16 + ldmatrix): 128x128 tile, BK=32, 256 threads, 2-stage.
// ---------------------------------------------------------------------------
#define QSH 5120   // 128*40 halves per tile stage

__device__ __forceinline__ void gload(__half* as_dst, __half* bs_dst,
                                      const __half* a_src, const __half* w_src,
                                      int tid)
{
#pragma unroll
    for (int u = 0; u < 2; u++) {
        int c = u * 256 + tid;
        int row = c >> 2, off = (c & 3) * 8;
        cpa16(&as_dst[row * 40 + off], &a_src[(size_t)row * 768 + off]);
        cpa16(&bs_dst[row * 40 + off], &w_src[(size_t)row * 768 + off]);
    }
}

__global__ __launch_bounds__(256, 2) void qkv_tc()
{
    extern __shared__ __half smh[];
    __half* As = smh;               // [2][128*40]
    __half* Bs = smh + 2 * QSH;

    const int tid = threadIdx.x;
    const int m0 = blockIdx.y * 128;
    const int n0 = blockIdx.x * 128;

    const int warp = tid >> 5;
    const int lane = tid & 31;
    const int wm = warp >> 1;
    const int wn = warp & 1;
    const int mb = wm * 32;
    const int nb = wn * 64;
    const int gr = lane >> 2;
    const int tc = lane & 3;
    const int q  = lane >> 3;
    const int r8 = lane & 7;
    const int arow = (q & 1) * 8 + r8;
    const int acol = (q >> 1) * 8;
    const int brow = (q >> 1) * 8 + r8;
    const int bcol = (q & 1) * 8;

    const __half* Abase = g_x + (size_t)m0 * 768;
    const __half* Wbase = g_wqkv + (size_t)n0 * 768;

    float acc[2][8][4];
#pragma unroll
    for (int mt = 0; mt < 2; mt++)
#pragma unroll
        for (int nt = 0; nt < 8; nt++)
#pragma unroll
            for (int i = 0; i < 4; i++) acc[mt][nt][i] = 0.f;

    gload(As, Bs, Abase, Wbase, tid);
    cp_commit();

    for (int kt = 0; kt < 24; kt++) {
        if (kt + 1 < 24) {
            int st = (kt + 1) & 1;
            int k0 = (kt + 1) * 32;
            gload(As + st * QSH, Bs + st * QSH, Abase + k0, Wbase + k0, tid);
            cp_commit();
            cp_wait1();
        } else {
            cp_wait0();
        }
        __syncthreads();

        const __half* Asf = As + (kt & 1) * QSH;
        const __half* Bsf = Bs + (kt & 1) * QSH;

        unsigned a[2][2][4];
#pragma unroll
        for (int mt = 0; mt < 2; mt++)
#pragma unroll
            for (int ks = 0; ks < 2; ks++)
                ldm4(a[mt][ks], Asf + (mb + mt * 16 + arow) * 40 + ks * 16 + acol);

#pragma unroll
        for (int ks = 0; ks < 2; ks++) {
#pragma unroll
            for (int ntp = 0; ntp < 4; ntp++) {
                unsigned d[4];
                ldm4(d, Bsf + (nb + ntp * 16 + brow) * 40 + ks * 16 + bcol);
                mma16(acc[0][ntp * 2],     a[0][ks][0], a[0][ks][1], a[0][ks][2], a[0][ks][3], d[0], d[1]);
                mma16(acc[0][ntp * 2 + 1], a[0][ks][0], a[0][ks][1], a[0][ks][2], a[0][ks][3], d[2], d[3]);
                mma16(acc[1][ntp * 2],     a[1][ks][0], a[1][ks][1], a[1][ks][2], a[1][ks][3], d[0], d[1]);
                mma16(acc[1][ntp * 2 + 1], a[1][ks][0], a[1][ks][1], a[1][ks][2], a[1][ks][3], d[2], d[3]);
            }
        }
        __syncthreads();
    }

    // Epilogue
#pragma unroll
    for (int mt = 0; mt < 2; mt++) {
        int mg = m0 + mb + mt * 16 + gr;
#pragma unroll
        for (int nt = 0; nt < 8; nt++) {
            int f = n0 + nb + nt * 8 + tc * 2;
            int t = f / 768;
            int fr = f - t * 768;
            int h = fr >> 6;
            int d = fr & 63;
            int bb = mg >> 10;
            int l = mg & 1023;
            if (t == 2) {
                size_t vb = ((size_t)(bb * H_ + h) * D_ + d) * L_ + l;
                g_vt[vb]           = __float2half_rn(acc[mt][nt][0]);
                g_vt[vb + L_]      = __float2half_rn(acc[mt][nt][1]);
                g_vt[vb + 8]       = __float2half_rn(acc[mt][nt][2]);
                g_vt[vb + L_ + 8]  = __float2half_rn(acc[mt][nt][3]);
            } else {
                float s = (t == 0) ? 0.125f : 1.0f;
                __half* dst = (t == 0) ? g_q : g_k;
                size_t base = ((size_t)(bb * H_ + h) * L_ + l) * D_ + d;
                *(unsigned*)&dst[base] = f2h2(acc[mt][nt][0] * s, acc[mt][nt][1] * s);
                *(unsigned*)&dst[base + 8 * D_] = f2h2(acc[mt][nt][2] * s, acc[mt][nt][3] * s);
            }
        }
    }
}

// ---------------------------------------------------------------------------
// Fused attention per (b,h): QK^T + softmax + attn write + PV.
// 32 q-rows per block, 512 threads. Scores fp32 in regs; normalized P staged
// ONCE as fp16 into smem (values identical to the old pv_tc fragment cvt);
// PV streams V^T tiles through the K buffers, A frags via ldmatrix from Ps.
// pv_tc and its 201MB attn re-read are gone.
// ---------------------------------------------------------------------------
#define KSH 9216    // 128*72 halves per K/V stage
#define PSTR 1032   // P staging row stride in halves (2064B; rows 4w apart mod 32)
#define VSTR 136    // V^T tile row stride in halves

__device__ __forceinline__ void kvload(__half* dst, const __half* src, int tid)
{
#pragma unroll
    for (int u = 0; u < 2; u++) {
        int c = u * 512 + tid;
        int row = c >> 3, off = (c & 7) * 8;
        cpa16(&dst[row * 72 + off], &src[(size_t)row * D_ + off]);
    }
}
// V^T tile: 64 rows (d) x 128 cols (l), row stride VSTR
__device__ __forceinline__ void vload(__half* dst, const __half* src, int tid)
{
#pragma unroll
    for (int u = 0; u < 2; u++) {
        int c = u * 512 + tid;
        int row = c >> 4, off = (c & 15) * 8;
        cpa16(&dst[row * VSTR + off], &src[(size_t)row * L_ + off]);
    }
}

__global__ __launch_bounds__(512) void attn_tc(float* __restrict__ attn_out)
{
    extern __shared__ __half smh[];
    __half* Ks   = smh;                         // [2][KSH] K tiles, then V tiles
    float* sredm = (float*)(smh + 2 * KSH);     // [32][8]
    float* sreds = sredm + 256;                 // [32][8]
    __half* Ps   = smh + 2 * KSH + 1024;        // [32][PSTR] fp16 P

    const int bh = blockIdx.y;
    const int m0 = blockIdx.x * 32;
    const int tid = threadIdx.x;
    const int warp = tid >> 5;
    const int lane = tid & 31;
    const int gr = lane >> 2;
    const int tc = lane & 3;
    const int mtA = warp & 1;       // 16-row half
    const int cg  = warp >> 1;      // 0..7 column group
    const int q   = lane >> 3;
    const int r8  = lane & 7;
    const int arow = (q & 1) * 8 + r8;
    const int acol = (q >> 1) * 8;
    const int brow = (q >> 1) * 8 + r8;
    const int bcol = (q & 1) * 8;

    const size_t head_base = (size_t)bh * L_ * D_;
    const __half* qb = g_q + head_base;
    const __half* kb = g_k + head_base;

    // Q fragments from gmem (fp16, pre-scaled). k=64 -> 4 k16 steps.
    unsigned qa[4][4];
    {
        const unsigned* r0 = (const unsigned*)(qb + (size_t)(m0 + mtA * 16 + gr) * D_);
        const unsigned* r1 = (const unsigned*)(qb + (size_t)(m0 + mtA * 16 + gr + 8) * D_);
#pragma unroll
        for (int ks = 0; ks < 4; ks++) {
            qa[ks][0] = r0[ks * 8 + tc];
            qa[ks][1] = r1[ks * 8 + tc];
            qa[ks][2] = r0[ks * 8 + tc + 4];
            qa[ks][3] = r1[ks * 8 + tc + 4];
        }
    }

    float sc[8][2][4];
#pragma unroll
    for (int t = 0; t < 8; t++)
#pragma unroll
        for (int nt = 0; nt < 2; nt++)
#pragma unroll
            for (int i = 0; i < 4; i++) sc[t][nt][i] = 0.f;

    kvload(Ks, kb, tid);
    cp_commit();

    // ---- Phase A: scores ----
    for (int t = 0; t < 8; t++) {
        if (t + 1 < 8) {
            kvload(Ks + ((t + 1) & 1) * KSH, kb + (size_t)(t + 1) * 128 * D_, tid);
            cp_commit();
            cp_wait1();
        } else {
            cp_wait0();
        }
        __syncthreads();

        const __half* Ksf = Ks + (t & 1) * KSH;
#pragma unroll
        for (int ks = 0; ks < 4; ks++) {
            unsigned d[4];
            ldm4(d, Ksf + (cg * 16 + brow) * 72 + ks * 16 + bcol);
            mma16(sc[t][0], qa[ks][0], qa[ks][1], qa[ks][2], qa[ks][3], d[0], d[1]);
            mma16(sc[t][1], qa[ks][0], qa[ks][1], qa[ks][2], qa[ks][3], d[2], d[3]);
        }
        __syncthreads();
    }

    // ---- Phase B: softmax ----
    const int rA = mtA * 16 + gr;
    const int rB = rA + 8;

    float mxA = -1e30f, mxB = -1e30f;
#pragma unroll
    for (int t = 0; t < 8; t++)
#pragma unroll
        for (int nt = 0; nt < 2; nt++) {
            mxA = fmaxf(mxA, fmaxf(sc[t][nt][0], sc[t][nt][1]));
            mxB = fmaxf(mxB, fmaxf(sc[t][nt][2], sc[t][nt][3]));
        }
    mxA = fmaxf(mxA, __shfl_xor_sync(0xffffffffu, mxA, 1));
    mxA = fmaxf(mxA, __shfl_xor_sync(0xffffffffu, mxA, 2));
    mxB = fmaxf(mxB, __shfl_xor_sync(0xffffffffu, mxB, 1));
    mxB = fmaxf(mxB, __shfl_xor_sync(0xffffffffu, mxB, 2));
    if (tc == 0) {
        sredm[rA * 8 + cg] = mxA;
        sredm[rB * 8 + cg] = mxB;
    }
    __syncthreads();
    mxA = sredm[rA * 8];
    mxB = sredm[rB * 8];
#pragma unroll
    for (int j = 1; j < 8; j++) {
        mxA = fmaxf(mxA, sredm[rA * 8 + j]);
        mxB = fmaxf(mxB, sredm[rB * 8 + j]);
    }

    float sA = 0.f, sB = 0.f;
#pragma unroll
    for (int t = 0; t < 8; t++)
#pragma unroll
        for (int nt = 0; nt < 2; nt++) {
            sc[t][nt][0] = __expf(sc[t][nt][0] - mxA);
            sc[t][nt][1] = __expf(sc[t][nt][1] - mxA);
            sc[t][nt][2] = __expf(sc[t][nt][2] - mxB);
            sc[t][nt][3] = __expf(sc[t][nt][3] - mxB);
            sA += sc[t][nt][0] + sc[t][nt][1];
            sB += sc[t][nt][2] + sc[t][nt][3];
        }
    sA += __shfl_xor_sync(0xffffffffu, sA, 1);
    sA += __shfl_xor_sync(0xffffffffu, sA, 2);
    sB += __shfl_xor_sync(0xffffffffu, sB, 1);
    sB += __shfl_xor_sync(0xffffffffu, sB, 2);
    if (tc == 0) {
        sreds[rA * 8 + cg] = sA;
        sreds[rB * 8 + cg] = sB;
    }
    __syncthreads();
    sA = 0.f; sB = 0.f;
#pragma unroll
    for (int j = 0; j < 8; j++) {
        sA += sreds[rA * 8 + j];
        sB += sreds[rB * 8 + j];
    }
    const float invA = 1.0f / sA;
    const float invB = 1.0f / sB;

    // ---- attn write (fp32, once) + P staging (fp16 smem) ----
    float* rowA = attn_out + (size_t)bh * L_ * L_ + (size_t)(m0 + rA) * L_;
    float* rowB = attn_out + (size_t)bh * L_ * L_ + (size_t)(m0 + rB) * L_;
#pragma unroll
    for (int t = 0; t < 8; t++)
#pragma unroll
        for (int nt = 0; nt < 2; nt++) {
            int col = t * 128 + cg * 16 + nt * 8 + tc * 2;
            float pA0 = sc[t][nt][0] * invA, pA1 = sc[t][nt][1] * invA;
            float pB0 = sc[t][nt][2] * invB, pB1 = sc[t][nt][3] * invB;
            *(float2*)&rowA[col] = make_float2(pA0, pA1);
            *(float2*)&rowB[col] = make_float2(pB0, pB1);
            *(unsigned*)&Ps[rA * PSTR + col] = f2h2(pA0, pA1);
            *(unsigned*)&Ps[rB * PSTR + col] = f2h2(pB0, pB1);
        }

    // ---- Phase C: O = P V (A from Ps via ldmatrix, V^T streamed) ----
    const __half* vtb = g_vt + (size_t)bh * D_ * L_;
    vload(Ks, vtb, tid);   // V tile 0 -> stage 0
    cp_commit();

    const int mtC = warp >> 3;
    const int nC = (warp & 7) * 8;
    const int l16 = lane & 15;
    const int vrow = nC + (l16 & 7);
    const int vcolo = (l16 >> 3) * 8;

    float oacc[4] = {0.f, 0.f, 0.f, 0.f};

    for (int t = 0; t < 8; t++) {
        cp_wait0();
        __syncthreads();           // tile t landed; P staged; stage reuse safe
        if (t + 1 < 8) {
            vload(Ks + ((t + 1) & 1) * KSH, vtb + (t + 1) * 128, tid);
            cp_commit();
        }
        const __half* Vs = Ks + (t & 1) * KSH;
        const __half* Pb = Ps + (mtC * 16) * PSTR + t * 128;
#pragma unroll
        for (int ks = 0; ks < 8; ks++) {
            unsigned a[4];
            ldm4(a, Pb + arow * PSTR + ks * 16 + acol);
            unsigned b[2];
            ldm2(b, Vs + vrow * VSTR + ks * 16 + vcolo);
            mma16(oacc, a[0], a[1], a[2], a[3], b[0], b[1]);
        }
    }

    // ---- write O to g_o fp16 [B*L, C] (c = h*64 + d) ----
    {
        int bb = bh / H_;
        int h = bh % H_;
        int mg = m0 + mtC * 16 + gr;
        int d = nC + tc * 2;
        size_t addr = ((size_t)(bb * L_ + mg)) * C_ + h * D_ + d;
        *(unsigned*)&g_o[addr] = f2h2(oacc[0], oacc[1]);
        *(unsigned*)&g_o[addr + (size_t)8 * C_] = f2h2(oacc[2], oacc[3]);
    }
}

// ---------------------------------------------------------------------------
// Projection GEMM (fp16 + ldmatrix): 128m x 64n tiles (384 blocks), BK=32,
// 256 threads, 2-stage, 3 blocks/SM. fp32 accumulate + fp32 store.
// ---------------------------------------------------------------------------
#define PAH 5120   // 128*40 halves (A stage)
#define PBH 2560   // 64*40 halves (B stage)

__device__ __forceinline__ void projload(__half* as_dst, __half* bs_dst,
                                         const __half* a_src, const __half* w_src,
                                         int tid)
{
#pragma unroll
    for (int u = 0; u < 2; u++) {
        int c = u * 256 + tid;
        int row = c >> 2, off = (c & 3) * 8;
        cpa16(&as_dst[row * 40 + off], &a_src[(size_t)row * 768 + off]);
    }
    {
        int row = tid >> 2, off = (tid & 3) * 8;
        cpa16(&bs_dst[row * 40 + off], &w_src[(size_t)row * 768 + off]);
    }
}

__global__ __launch_bounds__(256, 3) void proj_tc(const float* __restrict__ bias,
                                                  float* __restrict__ out)
{
    extern __shared__ __half smq[];
    __half* As = smq;                // [2][128*40]
    __half* Bs = smq + 2 * PAH;      // [2][64*40]

    const int tid = threadIdx.x;
    const int m0 = blockIdx.y * 128;
    const int n0 = blockIdx.x * 64;
    const int warp = tid >> 5;
    const int lane = tid & 31;
    const int gr = lane >> 2;
    const int tc = lane & 3;
    const int wm = warp >> 1;
    const int wn = warp & 1;
    const int q  = lane >> 3;
    const int r8 = lane & 7;
    const int arow = (q & 1) * 8 + r8;
    const int acol = (q >> 1) * 8;
    const int brow = (q >> 1) * 8 + r8;
    const int bcol = (q & 1) * 8;

    const __half* Ab = g_o + (size_t)m0 * 768;
    const __half* Wb = g_wproj + (size_t)n0 * 768;

    float acc[2][4][4];
#pragma unroll
    for (int mt = 0; mt < 2; mt++)
#pragma unroll
        for (int nt = 0; nt < 4; nt++)
#pragma unroll
            for (int i = 0; i < 4; i++) acc[mt][nt][i] = 0.f;

    projload(As, Bs, Ab, Wb, tid);
    cp_commit();

    for (int kt = 0; kt < 24; kt++) {
        if (kt + 1 < 24) {
            int st = (kt + 1) & 1;
            int k0 = (kt + 1) * 32;
            projload(As + st * PAH, Bs + st * PBH, Ab + k0, Wb + k0, tid);
            cp_commit();
            cp_wait1();
        } else {
            cp_wait0();
        }
        __syncthreads();

        const __half* Asf = As + (kt & 1) * PAH;
        const __half* Bsf = Bs + (kt & 1) * PBH;

        unsigned a[2][2][4];
#pragma unroll
        for (int mt = 0; mt < 2; mt++)
#pragma unroll
            for (int ks = 0; ks < 2; ks++)
                ldm4(a[mt][ks], Asf + (wm * 32 + mt * 16 + arow) * 40 + ks * 16 + acol);

#pragma unroll
        for (int ks = 0; ks < 2; ks++) {
#pragma unroll
            for (int ntp = 0; ntp < 2; ntp++) {
                unsigned d[4];
                ldm4(d, Bsf + (wn * 32 + ntp * 16 + brow) * 40 + ks * 16 + bcol);
                mma16(acc[0][ntp * 2],     a[0][ks][0], a[0][ks][1], a[0][ks][2], a[0][ks][3], d[0], d[1]);
                mma16(acc[0][ntp * 2 + 1], a[0][ks][0], a[0][ks][1], a[0][ks][2], a[0][ks][3], d[2], d[3]);
                mma16(acc[1][ntp * 2],     a[1][ks][0], a[1][ks][1], a[1][ks][2], a[1][ks][3], d[0], d[1]);
                mma16(acc[1][ntp * 2 + 1], a[1][ks][0], a[1][ks][1], a[1][ks][2], a[1][ks][3], d[2], d[3]);
            }
        }
        __syncthreads();
    }

    // Epilogue: bias + fp32 store
#pragma unroll
    for (int mt = 0; mt < 2; mt++) {
        int mg = m0 + wm * 32 + mt * 16 + gr;
#pragma unroll
        for (int nt = 0; nt < 4; nt++) {
            int f = n0 + wn * 32 + nt * 8 + tc * 2;
            float2 bv = *(const float2*)&bias[f];
            size_t base = (size_t)mg * 768 + f;
            *(float2*)&out[base] =
                make_float2(acc[mt][nt][0] + bv.x, acc[mt][nt][1] + bv.y);
            *(float2*)&out[base + (size_t)8 * 768] =
                make_float2(acc[mt][nt][2] + bv.x, acc[mt][nt][3] + bv.y);
        }
    }
}

// ---------------------------------------------------------------------------
extern "C" void kernel_launch(void* const* d_in, const int* in_sizes, int n_in,
                              void* d_out, int out_size)
{
    const float* x      = (const float*)d_in[0];
    const float* w_qkv  = (const float*)d_in[1];
    const float* w_proj = (const float*)d_in[2];
    const float* b_proj = (const float*)d_in[3];

    float* out  = (float*)d_out;              // [B,L,C]
    float* attn = out + (size_t)M_ * C_;      // [B,H,L,L]

    const int qkv_smem  = 4 * QSH * (int)sizeof(__half);                      // 40960
    const int attn_smem = (2 * KSH + 1024 + 32 * PSTR) * (int)sizeof(__half); // 104960
    const int proj_smem = (2 * PAH + 2 * PBH) * (int)sizeof(__half);          // 30720

    cudaFuncSetAttribute(qkv_tc, cudaFuncAttributeMaxDynamicSharedMemorySize, qkv_smem);
    cudaFuncSetAttribute(attn_tc, cudaFuncAttributeMaxDynamicSharedMemorySize, attn_smem);
    cudaFuncSetAttribute(proj_tc, cudaFuncAttributeMaxDynamicSharedMemorySize, proj_smem);

    // 0. Convert inputs to fp16
    round_fp16<<<(NX4 + NWQ4 + NWP4) / 256, 256>>>(x, w_qkv, w_proj);

    // 1. QKV projection (fp16 mma + ldmatrix; v stored transposed)
    qkv_tc<<<dim3(NQKV_ / 128, M_ / 128), 256, qkv_smem>>>();

    // 2. Fused attention: scores + softmax + attn write + PV (no P round-trip)
    attn_tc<<<dim3(L_ / 32, B_ * H_), 512, attn_smem>>>(attn);

    // 3. Output projection + bias (fp16 mma + ldmatrix, fp32 out)
    proj_tc<<<dim3(C_ / 64, M_ / 128), 256, proj_smem>>>(b_proj, out);
}

// round 16
// speedup vs baseline: 1.1097x; 1.1097x over previous
#include <cuda_runtime.h>
#include <cuda_fp16.h>

// Problem constants
#define B_ 4
#define L_ 1024
#define C_ 768
#define H_ 12
#define D_ 64
#define M_ (B_ * L_)      // 4096
#define NQKV_ (3 * C_)    // 2304

// Scratch (device globals; no allocation allowed)
__device__ __half g_q[B_ * H_ * L_ * D_];   // [B,H,L,D], fp16, q pre-scaled
__device__ __half g_k[B_ * H_ * L_ * D_];   // [B,H,L,D], fp16
__device__ __half g_vt[B_ * H_ * D_ * L_];  // [B,H,D,L]  V TRANSPOSED, fp16
__device__ __half g_o[M_ * C_];             // attention output, fp16
__device__ __half g_x[M_ * C_];             // fp16 x
__device__ __half g_wqkv[NQKV_ * C_];       // fp16 w_qkv
__device__ __half g_wproj[C_ * C_];         // fp16 w_proj

// ---- helpers -----------------------------------------------------------
__device__ __forceinline__ unsigned f2h2(float lo, float hi) {
    __half2 h = __floats2half2_rn(lo, hi);
    return *(unsigned*)&h;
}

// mma.m16n8k16 row.col f32 += f16*f16
__device__ __forceinline__ void mma16(float* c, unsigned a0, unsigned a1,
                                      unsigned a2, unsigned a3,
                                      unsigned b0, unsigned b1) {
    asm volatile(
        "mma.sync.aligned.m16n8k16.row.col.f32.f16.f16.f32 "
        "{%0,%1,%2,%3},{%4,%5,%6,%7},{%8,%9},{%0,%1,%2,%3};"
        : "+f"(c[0]), "+f"(c[1]), "+f"(c[2]), "+f"(c[3])
        : "r"(a0), "r"(a1), "r"(a2), "r"(a3), "r"(b0), "r"(b1));
}
__device__ __forceinline__ void ldm4(unsigned* d, const __half* p) {
    unsigned sa = (unsigned)__cvta_generic_to_shared(p);
    asm volatile("ldmatrix.sync.aligned.m8n8.x4.shared.b16 {%0,%1,%2,%3}, [%4];"
        : "=r"(d[0]), "=r"(d[1]), "=r"(d[2]), "=r"(d[3]) : "r"(sa));
}
__device__ __forceinline__ void cpa16(void* s, const void* g) {
    unsigned sa = (unsigned)__cvta_generic_to_shared(s);
    asm volatile("cp.async.cg.shared.global [%0], [%1], 16;" :: "r"(sa), "l"(g));
}
__device__ __forceinline__ void cp_commit() {
    asm volatile("cp.async.commit_group;" ::: "memory");
}
__device__ __forceinline__ void cp_wait1() {
    asm volatile("cp.async.wait_group 1;" ::: "memory");
}
__device__ __forceinline__ void cp_wait0() {
    asm volatile("cp.async.wait_group 0;" ::: "memory");
}

// ---------------------------------------------------------------------------
// Kernel 0: convert x, w_qkv, w_proj to fp16.
// ---------------------------------------------------------------------------
#define NX4  (M_ * C_ / 4)
#define NWQ4 (NQKV_ * C_ / 4)
#define NWP4 (C_ * C_ / 4)
__global__ __launch_bounds__(256) void round_fp16(const float* __restrict__ x,
                                                  const float* __restrict__ wq,
                                                  const float* __restrict__ wp)
{
    int i = blockIdx.x * 256 + threadIdx.x;
    const float4* src;
    unsigned* dst;
    int j;
    if (i < NX4)                  { src = (const float4*)x;  dst = (unsigned*)g_x;     j = i; }
    else if (i < NX4 + NWQ4)      { src = (const float4*)wq; dst = (unsigned*)g_wqkv;  j = i - NX4; }
    else                          { src = (const float4*)wp; dst = (unsigned*)g_wproj; j = i - NX4 - NWQ4; }
    float4 v = src[j];
    dst[j * 2]     = f2h2(v.x, v.y);
    dst[j * 2 + 1] = f2h2(v.z, v.w);
}

// ---------------------------------------------------------------------------
// QKV GEMM (fp16 + ldmatrix): 128x128 tile, BK=64, 256 threads, 2-stage.
// 12 iterations (half the barriers of BK=32), 8 cp.async chunks/thread/stage.
// Row stride 72 halves (144B): ldmatrix rows at 4r mod 32 -> conflict-free.
// ---------------------------------------------------------------------------
#define QSH 9216   // 128*72 halves per tile stage

__device__ __forceinline__ void gload(__half* as_dst, __half* bs_dst,
                                      const __half* a_src, const __half* w_src,
                                      int tid)
{
#pragma unroll
    for (int u = 0; u < 4; u++) {
        int c = u * 256 + tid;
        int row = c >> 3, off = (c & 7) * 8;
        cpa16(&as_dst[row * 72 + off], &a_src[(size_t)row * 768 + off]);
        cpa16(&bs_dst[row * 72 + off], &w_src[(size_t)row * 768 + off]);
    }
}

__global__ __launch_bounds__(256, 2) void qkv_tc()
{
    extern __shared__ __half smh[];
    __half* As = smh;               // [2][128*72]
    __half* Bs = smh + 2 * QSH;

    const int tid = threadIdx.x;
    const int m0 = blockIdx.y * 128;
    const int n0 = blockIdx.x * 128;

    const int warp = tid >> 5;
    const int lane = tid & 31;
    const int wm = warp >> 1;
    const int wn = warp & 1;
    const int mb = wm * 32;
    const int nb = wn * 64;
    const int gr = lane >> 2;
    const int tc = lane & 3;
    const int q  = lane >> 3;
    const int r8 = lane & 7;
    const int arow = (q & 1) * 8 + r8;
    const int acol = (q >> 1) * 8;
    const int brow = (q >> 1) * 8 + r8;
    const int bcol = (q & 1) * 8;

    const __half* Abase = g_x + (size_t)m0 * 768;
    const __half* Wbase = g_wqkv + (size_t)n0 * 768;

    float acc[2][8][4];
#pragma unroll
    for (int mt = 0; mt < 2; mt++)
#pragma unroll
        for (int nt = 0; nt < 8; nt++)
#pragma unroll
            for (int i = 0; i < 4; i++) acc[mt][nt][i] = 0.f;

    gload(As, Bs, Abase, Wbase, tid);
    cp_commit();

    for (int kt = 0; kt < 12; kt++) {
        if (kt + 1 < 12) {
            int st = (kt + 1) & 1;
            int k0 = (kt + 1) * 64;
            gload(As + st * QSH, Bs + st * QSH, Abase + k0, Wbase + k0, tid);
            cp_commit();
            cp_wait1();
        } else {
            cp_wait0();
        }
        __syncthreads();

        const __half* Asf = As + (kt & 1) * QSH;
        const __half* Bsf = Bs + (kt & 1) * QSH;

#pragma unroll
        for (int ks = 0; ks < 4; ks++) {
            unsigned a[2][4];
#pragma unroll
            for (int mt = 0; mt < 2; mt++)
                ldm4(a[mt], Asf + (mb + mt * 16 + arow) * 72 + ks * 16 + acol);
#pragma unroll
            for (int ntp = 0; ntp < 4; ntp++) {
                unsigned d[4];
                ldm4(d, Bsf + (nb + ntp * 16 + brow) * 72 + ks * 16 + bcol);
                mma16(acc[0][ntp * 2],     a[0][0], a[0][1], a[0][2], a[0][3], d[0], d[1]);
                mma16(acc[0][ntp * 2 + 1], a[0][0], a[0][1], a[0][2], a[0][3], d[2], d[3]);
                mma16(acc[1][ntp * 2],     a[1][0], a[1][1], a[1][2], a[1][3], d[0], d[1]);
                mma16(acc[1][ntp * 2 + 1], a[1][0], a[1][1], a[1][2], a[1][3], d[2], d[3]);
            }
        }
        __syncthreads();
    }

    // Epilogue
#pragma unroll
    for (int mt = 0; mt < 2; mt++) {
        int mg = m0 + mb + mt * 16 + gr;
#pragma unroll
        for (int nt = 0; nt < 8; nt++) {
            int f = n0 + nb + nt * 8 + tc * 2;
            int t = f / 768;
            int fr = f - t * 768;
            int h = fr >> 6;
            int d = fr & 63;
            int bb = mg >> 10;
            int l = mg & 1023;
            if (t == 2) {
                size_t vb = ((size_t)(bb * H_ + h) * D_ + d) * L_ + l;
                g_vt[vb]           = __float2half_rn(acc[mt][nt][0]);
                g_vt[vb + L_]      = __float2half_rn(acc[mt][nt][1]);
                g_vt[vb + 8]       = __float2half_rn(acc[mt][nt][2]);
                g_vt[vb + L_ + 8]  = __float2half_rn(acc[mt][nt][3]);
            } else {
                float s = (t == 0) ? 0.125f : 1.0f;
                __half* dst = (t == 0) ? g_q : g_k;
                size_t base = ((size_t)(bb * H_ + h) * L_ + l) * D_ + d;
                *(unsigned*)&dst[base] = f2h2(acc[mt][nt][0] * s, acc[mt][nt][1] * s);
                *(unsigned*)&dst[base + 8 * D_] = f2h2(acc[mt][nt][2] * s, acc[mt][nt][3] * s);
            }
        }
    }
}

// ---------------------------------------------------------------------------
// Attention scores kernel (fp16 QK + ldmatrix K frags): 32 q-rows per block,
// 512 threads, 2-stage K pipeline. (R14 configuration, unchanged.)
// ---------------------------------------------------------------------------
#define KSH 9216   // 128*72 halves per stage

__device__ __forceinline__ void kvload(__half* dst, const __half* src, int tid)
{
#pragma unroll
    for (int u = 0; u < 2; u++) {
        int c = u * 512 + tid;
        int row = c >> 3, off = (c & 7) * 8;
        cpa16(&dst[row * 72 + off], &src[(size_t)row * D_ + off]);
    }
}

__global__ __launch_bounds__(512) void attn_tc(float* __restrict__ attn_out)
{
    extern __shared__ __half smh[];
    __half* Ks   = smh;                         // [2][128*72]
    float* sredm = (float*)(smh + 2 * KSH);     // [32][8]
    float* sreds = sredm + 256;                 // [32][8]

    const int bh = blockIdx.y;
    const int m0 = blockIdx.x * 32;
    const int tid = threadIdx.x;
    const int warp = tid >> 5;
    const int lane = tid & 31;
    const int gr = lane >> 2;
    const int tc = lane & 3;
    const int mtA = warp & 1;       // 16-row half
    const int cg  = warp >> 1;      // 0..7 column group
    const int q   = lane >> 3;
    const int r8  = lane & 7;
    const int brow = (q >> 1) * 8 + r8;
    const int bcol = (q & 1) * 8;

    const size_t head_base = (size_t)bh * L_ * D_;
    const __half* qb = g_q + head_base;
    const __half* kb = g_k + head_base;

    // Q fragments from gmem (fp16, pre-scaled). k=64 -> 4 k16 steps.
    unsigned qa[4][4];
    {
        const unsigned* r0 = (const unsigned*)(qb + (size_t)(m0 + mtA * 16 + gr) * D_);
        const unsigned* r1 = (const unsigned*)(qb + (size_t)(m0 + mtA * 16 + gr + 8) * D_);
#pragma unroll
        for (int ks = 0; ks < 4; ks++) {
            qa[ks][0] = r0[ks * 8 + tc];
            qa[ks][1] = r1[ks * 8 + tc];
            qa[ks][2] = r0[ks * 8 + tc + 4];
            qa[ks][3] = r1[ks * 8 + tc + 4];
        }
    }

    float sc[8][2][4];
#pragma unroll
    for (int t = 0; t < 8; t++)
#pragma unroll
        for (int nt = 0; nt < 2; nt++)
#pragma unroll
            for (int i = 0; i < 4; i++) sc[t][nt][i] = 0.f;

    kvload(Ks, kb, tid);
    cp_commit();

    for (int t = 0; t < 8; t++) {
        if (t + 1 < 8) {
            kvload(Ks + ((t + 1) & 1) * KSH, kb + (size_t)(t + 1) * 128 * D_, tid);
            cp_commit();
            cp_wait1();
        } else {
            cp_wait0();
        }
        __syncthreads();

        const __half* Ksf = Ks + (t & 1) * KSH;
#pragma unroll
        for (int ks = 0; ks < 4; ks++) {
            unsigned d[4];
            ldm4(d, Ksf + (cg * 16 + brow) * 72 + ks * 16 + bcol);
            mma16(sc[t][0], qa[ks][0], qa[ks][1], qa[ks][2], qa[ks][3], d[0], d[1]);
            mma16(sc[t][1], qa[ks][0], qa[ks][1], qa[ks][2], qa[ks][3], d[2], d[3]);
        }
        __syncthreads();
    }

    // ---- softmax over registers ----
    const int rA = mtA * 16 + gr;
    const int rB = rA + 8;

    float mxA = -1e30f, mxB = -1e30f;
#pragma unroll
    for (int t = 0; t < 8; t++)
#pragma unroll
        for (int nt = 0; nt < 2; nt++) {
            mxA = fmaxf(mxA, fmaxf(sc[t][nt][0], sc[t][nt][1]));
            mxB = fmaxf(mxB, fmaxf(sc[t][nt][2], sc[t][nt][3]));
        }
    mxA = fmaxf(mxA, __shfl_xor_sync(0xffffffffu, mxA, 1));
    mxA = fmaxf(mxA, __shfl_xor_sync(0xffffffffu, mxA, 2));
    mxB = fmaxf(mxB, __shfl_xor_sync(0xffffffffu, mxB, 1));
    mxB = fmaxf(mxB, __shfl_xor_sync(0xffffffffu, mxB, 2));
    if (tc == 0) {
        sredm[rA * 8 + cg] = mxA;
        sredm[rB * 8 + cg] = mxB;
    }
    __syncthreads();
    mxA = sredm[rA * 8];
    mxB = sredm[rB * 8];
#pragma unroll
    for (int j = 1; j < 8; j++) {
        mxA = fmaxf(mxA, sredm[rA * 8 + j]);
        mxB = fmaxf(mxB, sredm[rB * 8 + j]);
    }

    float sA = 0.f, sB = 0.f;
#pragma unroll
    for (int t = 0; t < 8; t++)
#pragma unroll
        for (int nt = 0; nt < 2; nt++) {
            sc[t][nt][0] = __expf(sc[t][nt][0] - mxA);
            sc[t][nt][1] = __expf(sc[t][nt][1] - mxA);
            sc[t][nt][2] = __expf(sc[t][nt][2] - mxB);
            sc[t][nt][3] = __expf(sc[t][nt][3] - mxB);
            sA += sc[t][nt][0] + sc[t][nt][1];
            sB += sc[t][nt][2] + sc[t][nt][3];
        }
    sA += __shfl_xor_sync(0xffffffffu, sA, 1);
    sA += __shfl_xor_sync(0xffffffffu, sA, 2);
    sB += __shfl_xor_sync(0xffffffffu, sB, 1);
    sB += __shfl_xor_sync(0xffffffffu, sB, 2);
    if (tc == 0) {
        sreds[rA * 8 + cg] = sA;
        sreds[rB * 8 + cg] = sB;
    }
    __syncthreads();
    sA = 0.f; sB = 0.f;
#pragma unroll
    for (int j = 0; j < 8; j++) {
        sA += sreds[rA * 8 + j];
        sB += sreds[rB * 8 + j];
    }
    const float invA = 1.0f / sA;
    const float invB = 1.0f / sB;

    // ---- write attn (fp32, exactly once) ----
    float* rowA = attn_out + (size_t)bh * L_ * L_ + (size_t)(m0 + rA) * L_;
    float* rowB = attn_out + (size_t)bh * L_ * L_ + (size_t)(m0 + rB) * L_;
#pragma unroll
    for (int t = 0; t < 8; t++)
#pragma unroll
        for (int nt = 0; nt < 2; nt++) {
            int col = t * 128 + cg * 16 + nt * 8 + tc * 2;
            *(float2*)&rowA[col] = make_float2(sc[t][nt][0] * invA, sc[t][nt][1] * invA);
            *(float2*)&rowB[col] = make_float2(sc[t][nt][2] * invB, sc[t][nt][3] * invB);
        }
}

// ---------------------------------------------------------------------------
// PV GEMM: O = P * V. A = attn (fp32 gmem -> fp16 cvt at fragment load),
// B = g_vt fp16 [d][l]. 128m x 64n tiles (384 blocks), BK=32, 256 threads,
// cp.async 2-stage, 3 blocks/SM. (R14 configuration; DRAM-floor-bound.)
// ---------------------------------------------------------------------------
#define PAST 4608   // 128*36 floats (A stage)
#define PBH  2560   // 64*40 halves (B stage)

__device__ __forceinline__ void pvload(float* as_dst, __half* bs_dst,
                                       const float* a_src, const __half* b_src,
                                       int tid)
{
#pragma unroll
    for (int u = 0; u < 4; u++) {
        int c = u * 256 + tid;
        int row = c >> 3, off = (c & 7) * 4;
        cpa16(&as_dst[row * 36 + off], &a_src[(size_t)row * 1024 + off]);
    }
    {
        int row = tid >> 2, off = (tid & 3) * 8;
        cpa16(&bs_dst[row * 40 + off], &b_src[(size_t)row * 1024 + off]);
    }
}

__global__ __launch_bounds__(256, 3) void pv_tc(const float* __restrict__ attn)
{
    extern __shared__ float smp[];
    float* As  = smp;                           // [2][128*36] fp32
    __half* Bs = (__half*)(smp + 2 * PAST);     // [2][64*40] fp16

    const int bh = blockIdx.y;
    const int m0 = blockIdx.x * 128;
    const int tid = threadIdx.x;
    const int warp = tid >> 5;
    const int lane = tid & 31;
    const int gr = lane >> 2;
    const int tc = lane & 3;
    const int wm = warp >> 1;   // 0..3
    const int wn = warp & 1;    // 0..1

    const float* Ab = attn + (size_t)bh * L_ * L_ + (size_t)m0 * 1024;
    const __half* Bb = g_vt + (size_t)bh * D_ * L_;

    float acc[2][4][4];
#pragma unroll
    for (int mt = 0; mt < 2; mt++)
#pragma unroll
        for (int nt = 0; nt < 4; nt++)
#pragma unroll
            for (int i = 0; i < 4; i++) acc[mt][nt][i] = 0.f;

    pvload(As, Bs, Ab, Bb, tid);
    cp_commit();

    for (int kt = 0; kt < 32; kt++) {
        if (kt + 1 < 32) {
            int st = (kt + 1) & 1;
            int k0 = (kt + 1) * 32;
            pvload(As + st * PAST, Bs + st * PBH, Ab + k0, Bb + k0, tid);
            cp_commit();
            cp_wait1();
        } else {
            cp_wait0();
        }
        __syncthreads();

        const float* Af = As + (kt & 1) * PAST;
        const unsigned* Bu = (const unsigned*)(Bs + (kt & 1) * PBH);
#pragma unroll
        for (int ks = 0; ks < 2; ks++) {
            unsigned a[2][4];
#pragma unroll
            for (int mt = 0; mt < 2; mt++) {
                int m = wm * 32 + mt * 16 + gr;
                float2 p0 = *(const float2*)&Af[m * 36 + ks * 16 + 2 * tc];
                float2 p1 = *(const float2*)&Af[(m + 8) * 36 + ks * 16 + 2 * tc];
                float2 p2 = *(const float2*)&Af[m * 36 + ks * 16 + 2 * tc + 8];
                float2 p3 = *(const float2*)&Af[(m + 8) * 36 + ks * 16 + 2 * tc + 8];
                a[mt][0] = f2h2(p0.x, p0.y);
                a[mt][1] = f2h2(p1.x, p1.y);
                a[mt][2] = f2h2(p2.x, p2.y);
                a[mt][3] = f2h2(p3.x, p3.y);
            }
#pragma unroll
            for (int nt = 0; nt < 4; nt++) {
                int n = wn * 32 + nt * 8 + gr;
                unsigned b0 = Bu[n * 20 + ks * 8 + tc];
                unsigned b1 = Bu[n * 20 + ks * 8 + tc + 4];
                mma16(acc[0][nt], a[0][0], a[0][1], a[0][2], a[0][3], b0, b1);
                mma16(acc[1][nt], a[1][0], a[1][1], a[1][2], a[1][3], b0, b1);
            }
        }
        __syncthreads();
    }

    // Epilogue -> g_o fp16 [B*L, C], c = h*64 + d
    const int bb = bh / H_;
    const int h = bh % H_;
#pragma unroll
    for (int mt = 0; mt < 2; mt++) {
        int mg = m0 + wm * 32 + mt * 16 + gr;
#pragma unroll
        for (int nt = 0; nt < 4; nt++) {
            int d = wn * 32 + nt * 8 + tc * 2;
            size_t addr = ((size_t)(bb * L_ + mg)) * C_ + h * D_ + d;
            *(unsigned*)&g_o[addr] = f2h2(acc[mt][nt][0], acc[mt][nt][1]);
            *(unsigned*)&g_o[addr + (size_t)8 * C_] = f2h2(acc[mt][nt][2], acc[mt][nt][3]);
        }
    }
}

// ---------------------------------------------------------------------------
// Projection GEMM (fp16 + ldmatrix): 128m x 64n tiles (384 blocks), BK=64,
// 12 iterations, 256 threads, 2-stage, 3 blocks/SM. fp32 accum + fp32 store.
// ---------------------------------------------------------------------------
#define PAH 9216   // 128*72 halves (A stage)
#define PBW 4608   // 64*72 halves (B stage)

__device__ __forceinline__ void projload(__half* as_dst, __half* bs_dst,
                                         const __half* a_src, const __half* w_src,
                                         int tid)
{
#pragma unroll
    for (int u = 0; u < 4; u++) {
        int c = u * 256 + tid;
        int row = c >> 3, off = (c & 7) * 8;
        cpa16(&as_dst[row * 72 + off], &a_src[(size_t)row * 768 + off]);
    }
#pragma unroll
    for (int u = 0; u < 2; u++) {
        int c = u * 256 + tid;
        int row = c >> 3, off = (c & 7) * 8;
        cpa16(&bs_dst[row * 72 + off], &w_src[(size_t)row * 768 + off]);
    }
}

__global__ __launch_bounds__(256, 3) void proj_tc(const float* __restrict__ bias,
                                                  float* __restrict__ out)
{
    extern __shared__ __half smq[];
    __half* As = smq;                // [2][128*72]
    __half* Bs = smq + 2 * PAH;      // [2][64*72]

    const int tid = threadIdx.x;
    const int m0 = blockIdx.y * 128;
    const int n0 = blockIdx.x * 64;
    const int warp = tid >> 5;
    const int lane = tid & 31;
    const int gr = lane >> 2;
    const int tc = lane & 3;
    const int wm = warp >> 1;
    const int wn = warp & 1;
    const int q  = lane >> 3;
    const int r8 = lane & 7;
    const int arow = (q & 1) * 8 + r8;
    const int acol = (q >> 1) * 8;
    const int brow = (q >> 1) * 8 + r8;
    const int bcol = (q & 1) * 8;

    const __half* Ab = g_o + (size_t)m0 * 768;
    const __half* Wb = g_wproj + (size_t)n0 * 768;

    float acc[2][4][4];
#pragma unroll
    for (int mt = 0; mt < 2; mt++)
#pragma unroll
        for (int nt = 0; nt < 4; nt++)
#pragma unroll
            for (int i = 0; i < 4; i++) acc[mt][nt][i] = 0.f;

    projload(As, Bs, Ab, Wb, tid);
    cp_commit();

    for (int kt = 0; kt < 12; kt++) {
        if (kt + 1 < 12) {
            int st = (kt + 1) & 1;
            int k0 = (kt + 1) * 64;
            projload(As + st * PAH, Bs + st * PBW, Ab + k0, Wb + k0, tid);
            cp_commit();
            cp_wait1();
        } else {
            cp_wait0();
        }
        __syncthreads();

        const __half* Asf = As + (kt & 1) * PAH;
        const __half* Bsf = Bs + (kt & 1) * PBW;

#pragma unroll
        for (int ks = 0; ks < 4; ks++) {
            unsigned a[2][4];
#pragma unroll
            for (int mt = 0; mt < 2; mt++)
                ldm4(a[mt], Asf + (wm * 32 + mt * 16 + arow) * 72 + ks * 16 + acol);
#pragma unroll
            for (int ntp = 0; ntp < 2; ntp++) {
                unsigned d[4];
                ldm4(d, Bsf + (wn * 32 + ntp * 16 + brow) * 72 + ks * 16 + bcol);
                mma16(acc[0][ntp * 2],     a[0][0], a[0][1], a[0][2], a[0][3], d[0], d[1]);
                mma16(acc[0][ntp * 2 + 1], a[0][0], a[0][1], a[0][2], a[0][3], d[2], d[3]);
                mma16(acc[1][ntp * 2],     a[1][0], a[1][1], a[1][2], a[1][3], d[0], d[1]);
                mma16(acc[1][ntp * 2 + 1], a[1][0], a[1][1], a[1][2], a[1][3], d[2], d[3]);
            }
        }
        __syncthreads();
    }

    // Epilogue: bias + fp32 store
#pragma unroll
    for (int mt = 0; mt < 2; mt++) {
        int mg = m0 + wm * 32 + mt * 16 + gr;
#pragma unroll
        for (int nt = 0; nt < 4; nt++) {
            int f = n0 + wn * 32 + nt * 8 + tc * 2;
            float2 bv = *(const float2*)&bias[f];
            size_t base = (size_t)mg * 768 + f;
            *(float2*)&out[base] =
                make_float2(acc[mt][nt][0] + bv.x, acc[mt][nt][1] + bv.y);
            *(float2*)&out[base + (size_t)8 * 768] =
                make_float2(acc[mt][nt][2] + bv.x, acc[mt][nt][3] + bv.y);
        }
    }
}

// ---------------------------------------------------------------------------
extern "C" void kernel_launch(void* const* d_in, const int* in_sizes, int n_in,
                              void* d_out, int out_size)
{
    const float* x      = (const float*)d_in[0];
    const float* w_qkv  = (const float*)d_in[1];
    const float* w_proj = (const float*)d_in[2];
    const float* b_proj = (const float*)d_in[3];

    float* out  = (float*)d_out;              // [B,L,C]
    float* attn = out + (size_t)M_ * C_;      // [B,H,L,L]

    const int qkv_smem  = 4 * QSH * (int)sizeof(__half);                  // 73728
    const int attn_smem = 2 * KSH * (int)sizeof(__half) + 512 * 4;        // 38912
    const int pv_smem   = 2 * PAST * 4 + 2 * PBH * (int)sizeof(__half);   // 47104
    const int proj_smem = (2 * PAH + 2 * PBW) * (int)sizeof(__half);      // 55296

    cudaFuncSetAttribute(qkv_tc, cudaFuncAttributeMaxDynamicSharedMemorySize, qkv_smem);
    cudaFuncSetAttribute(attn_tc, cudaFuncAttributeMaxDynamicSharedMemorySize, attn_smem);
    cudaFuncSetAttribute(pv_tc, cudaFuncAttributeMaxDynamicSharedMemorySize, pv_smem);
    cudaFuncSetAttribute(proj_tc, cudaFuncAttributeMaxDynamicSharedMemorySize, proj_smem);

    // 0. Convert inputs to fp16
    round_fp16<<<(NX4 + NWQ4 + NWP4) / 256, 256>>>(x, w_qkv, w_proj);

    // 1. QKV projection (fp16 mma + ldmatrix, BK=64; v stored transposed)
    qkv_tc<<<dim3(NQKV_ / 128, M_ / 128), 256, qkv_smem>>>();

    // 2. Scores + softmax + attn write (R14 config)
    attn_tc<<<dim3(L_ / 32, B_ * H_), 512, attn_smem>>>(attn);

    // 3. PV GEMM (R14 config; DRAM-floor-bound)
    pv_tc<<<dim3(L_ / 128, B_ * H_), 256, pv_smem>>>(attn);

    // 4. Output projection + bias (fp16 mma + ldmatrix, BK=64)
    proj_tc<<<dim3(C_ / 64, M_ / 128), 256, proj_smem>>>(b_proj, out);
}